// round 5
// baseline (speedup 1.0000x reference)
#include <cuda_runtime.h>
#include <cuda_bf16.h>
#include <math.h>

// Problem dims
#define B_   128
#define T_   512
#define E_   256
#define H_   512
#define G3   1536   // 3H (one direction's gate rows)
#define GT   3072   // both directions stacked

#define NCTA_REC    128
#define REC_THREADS 256

typedef unsigned long long ull;

// packed fp32x2 FMA: d.lo += a.lo*b.lo ; d.hi += a.hi*b.hi   (1 instr, 2 FMAs)
__device__ __forceinline__ void fma2(ull& d, ull a, ull b) {
    asm("fma.rn.f32x2 %0, %1, %2, %0;" : "+l"(d) : "l"(a), "l"(b));
}
__device__ __forceinline__ float2 u2f2(ull u) {
    float2 f; asm("mov.b64 {%0,%1}, %2;" : "=f"(f.x), "=f"(f.y) : "l"(u)); return f;
}
// static permutation of b within a 128-row: slot = [pair%4][pair/4][b&1]
__device__ __forceinline__ int permb(int b) {
    return ((b >> 1) & 3) * 32 + (b >> 3) * 2 + (b & 1);
}

// ---------------- scratch (device globals; no allocation allowed) ----------------
__device__ float g_xpT[(size_t)T_ * GT * B_];   // xpT[t][g][b], b innermost
__device__ float g_h[2 * H_ * B_];              // h[dir][j][slot]  (b PERMUTED)
__device__ float g_P[(size_t)GT * 4 * B_];      // P[g][kc][b] partials (natural b)
__device__ unsigned g_barcnt;
__device__ unsigned g_bargen;

// =================================================================================
// Phase 1: input projection, f32x2 microkernel.
// xpT[t][g][b] = sum_k W_ih[g][k] * emb[tok(b,t)][k] + b_ih[g]
// Grid (T_, GT/128), block 256, CTA tile 128g x 128b, microtile 8g x 8b (as 8x4 f32x2)
// =================================================================================
__global__ void __launch_bounds__(256, 2) proj_kernel(
    const int* __restrict__ inputs, const float* __restrict__ emb,
    const float* __restrict__ Wf, const float* __restrict__ Wb,
    const float* __restrict__ bf, const float* __restrict__ bb)
{
    __shared__ float Asd[16][256];          // [k][2g] duplicated (w,w) pairs
    __shared__ float Bsi[16][4][16][2];     // [k][pair%4][pair/4][half]
    __shared__ int   toks[128];

    const int t   = blockIdx.x;
    const int g0  = blockIdx.y * 128;
    const int tid = threadIdx.x;

    if (tid < 128) toks[tid] = inputs[tid * T_ + t];
    __syncthreads();

    const int    isB  = (g0 >= G3);
    const float* W    = isB ? Wb : Wf;
    const float* bias = isB ? bb : bf;
    const int    gl0  = g0 - (isB ? G3 : 0);

    const int tx = tid & 15;   // -> 8 b's (4 pairs)
    const int ty = tid >> 4;   // -> 8 g's

    ull acc[8][4];
    #pragma unroll
    for (int i = 0; i < 8; i++)
        #pragma unroll
        for (int m = 0; m < 4; m++) acc[i][m] = 0ull;

    for (int k0 = 0; k0 < E_; k0 += 16) {
        // W tile 128g x 16k -> Asd[k][2g] duplicated pairs
        #pragma unroll
        for (int l = 0; l < 2; l++) {
            int idx = tid * 2 + l;            // 0..511
            int row = idx >> 2, q = idx & 3;
            float4 v = *reinterpret_cast<const float4*>(
                &W[(size_t)(gl0 + row) * E_ + k0 + q * 4]);
            *reinterpret_cast<float2*>(&Asd[q*4+0][2*row]) = make_float2(v.x, v.x);
            *reinterpret_cast<float2*>(&Asd[q*4+1][2*row]) = make_float2(v.y, v.y);
            *reinterpret_cast<float2*>(&Asd[q*4+2][2*row]) = make_float2(v.z, v.z);
            *reinterpret_cast<float2*>(&Asd[q*4+3][2*row]) = make_float2(v.w, v.w);
        }
        // gathered emb tile 128b x 16k -> interleaved pair layout
        #pragma unroll
        for (int l = 0; l < 2; l++) {
            int idx = tid * 2 + l;
            int b = idx >> 2, q = idx & 3;
            float4 v = *reinterpret_cast<const float4*>(
                &emb[(size_t)toks[b] * E_ + k0 + q * 4]);
            int p = b >> 1, j = p & 3, txi = p >> 2, h = b & 1;
            Bsi[q*4+0][j][txi][h] = v.x;
            Bsi[q*4+1][j][txi][h] = v.y;
            Bsi[q*4+2][j][txi][h] = v.z;
            Bsi[q*4+3][j][txi][h] = v.w;
        }
        __syncthreads();

        #pragma unroll
        for (int k = 0; k < 16; k++) {
            ull af[8], bb2[4];
            #pragma unroll
            for (int i = 0; i < 8; i++)
                af[i] = *reinterpret_cast<const ull*>(&Asd[k][(ty*8 + i) * 2]);
            #pragma unroll
            for (int m = 0; m < 4; m++)
                bb2[m] = *reinterpret_cast<const ull*>(&Bsi[k][m][tx][0]);
            #pragma unroll
            for (int i = 0; i < 8; i++)
                #pragma unroll
                for (int m = 0; m < 4; m++)
                    fma2(acc[i][m], af[i], bb2[m]);
        }
        __syncthreads();
    }

    // Epilogue: +bias, write xpT[t][g][b] (b natural order: pairs are (2m,2m+1))
    #pragma unroll
    for (int i = 0; i < 8; i++) {
        int g = g0 + ty*8 + i;
        float bv = bias[gl0 + ty*8 + i];
        float2 a0 = u2f2(acc[i][0]), a1 = u2f2(acc[i][1]);
        float2 a2 = u2f2(acc[i][2]), a3 = u2f2(acc[i][3]);
        float* dst = &g_xpT[((size_t)t * GT + g) * B_ + tx*8];
        *reinterpret_cast<float4*>(dst)     = make_float4(a0.x+bv, a0.y+bv, a1.x+bv, a1.y+bv);
        *reinterpret_cast<float4*>(dst + 4) = make_float4(a2.x+bv, a2.y+bv, a3.x+bv, a3.y+bv);
    }
}

// =================================================================================
// Software grid barrier (128 CTAs, all co-resident at 1 CTA/SM)
// =================================================================================
__device__ __forceinline__ void grid_barrier() {
    __syncthreads();
    if (threadIdx.x == 0) {
        volatile unsigned* genp = &g_bargen;
        unsigned old = *genp;
        __threadfence();
        if (atomicAdd(&g_barcnt, 1u) == NCTA_REC - 1) {
            atomicExch(&g_barcnt, 0u);
            __threadfence();
            *genp = old + 1;
        } else {
            while (*genp == old) { __nanosleep(20); }
        }
    }
    __syncthreads();
}

// =================================================================================
// Phase 2: persistent recurrence, f32x2 phase-A microkernel.
// 128 CTAs = 32 gate-tiles (96 rows) x 4 k-chunks (128 k).
// g_h stores b in PERMUTED slot order -> phase-A h staging is a straight copy.
// =================================================================================
__global__ void __launch_bounds__(REC_THREADS, 1) rec_kernel(
    const float* __restrict__ Whf, const float* __restrict__ Whb,
    const float* __restrict__ bhf, const float* __restrict__ bhb)
{
    extern __shared__ float sm[];
    float* wsd = sm;               // [128 k][192] duplicated (w,w) pairs   96 KB
    float* hsi = sm + 128*192;     // [128 k][128 slots] permuted b         64 KB

    const int cta   = blockIdx.x;
    const int tid   = threadIdx.x;
    const int gtile = cta >> 2;
    const int kc    = cta & 3;
    const int gg0   = gtile * 96;
    const int dir   = (gg0 >= G3) ? 1 : 0;
    const int gl0   = gg0 - dir * G3;
    const float* Wh = dir ? Whb : Whf;

    // One-time: W_hh chunk -> SMEM, [k][2g] duplicated pairs
    for (int i = tid; i < 96*128; i += REC_THREADS) {
        int r = i >> 7, k = i & 127;
        float w = Wh[(size_t)(gl0 + r) * H_ + kc*128 + k];
        *reinterpret_cast<float2*>(&wsd[k*192 + 2*r]) = make_float2(w, w);
    }
    for (int i = cta*1024 + tid; i < cta*1024 + 1024; i += REC_THREADS)
        g_h[i] = 0.f;
    __threadfence();
    grid_barrier();

    const int tx  = tid & 15;      // -> 4 b-pairs
    const int ty  = tid >> 4;      // -> 6 g's
    const int wg0 = ty * 6;
    const int pb_b  = tid & 127;
    const int pb_sl = tid >> 7;
    const int pb_perm = permb(pb_b);

    for (int t = 0; t < T_; t++) {
        // ---- stage h chunk (already in permuted slot layout: straight copy)
        const float4* hsrc4 = reinterpret_cast<const float4*>(
            &g_h[dir * (H_ * B_) + kc * 128 * B_]);
        float4* hdst4 = reinterpret_cast<float4*>(hsi);
        for (int i = tid; i < 128*B_/4; i += REC_THREADS)
            hdst4[i] = __ldcg(hsrc4 + i);
        __syncthreads();

        ull acc[6][4];
        #pragma unroll
        for (int j = 0; j < 6; j++)
            #pragma unroll
            for (int m = 0; m < 4; m++) acc[j][m] = 0ull;

        #pragma unroll 4
        for (int k = 0; k < 128; k++) {
            ull hh[4], w2[6];
            #pragma unroll
            for (int m = 0; m < 4; m++)
                hh[m] = *reinterpret_cast<const ull*>(&hsi[k*128 + m*32 + tx*2]);
            #pragma unroll
            for (int j = 0; j < 6; j++)
                w2[j] = *reinterpret_cast<const ull*>(&wsd[k*192 + (wg0 + j)*2]);
            #pragma unroll
            for (int j = 0; j < 6; j++)
                #pragma unroll
                for (int m = 0; m < 4; m++)
                    fma2(acc[j][m], w2[j], hh[m]);
        }

        // partials: P[g][kc][b], natural b order (pairs (2m, 2m+1))
        #pragma unroll
        for (int j = 0; j < 6; j++) {
            int g = gg0 + wg0 + j;
            float2 a0 = u2f2(acc[j][0]), a1 = u2f2(acc[j][1]);
            float2 a2 = u2f2(acc[j][2]), a3 = u2f2(acc[j][3]);
            float* dst = &g_P[((size_t)g*4 + kc) * B_ + tx*8];
            __stcg(reinterpret_cast<float4*>(dst),
                   make_float4(a0.x, a0.y, a1.x, a1.y));
            __stcg(reinterpret_cast<float4*>(dst + 4),
                   make_float4(a2.x, a2.y, a3.x, a3.y));
        }
        __threadfence();
        grid_barrier();

        // ---- Phase B: gating; each thread owns 4 (dir,j) units for its b
        #pragma unroll
        for (int it = 0; it < 4; it++) {
            int v  = cta*8 + pb_sl*4 + it;   // 0..1023 = dir*512 + j
            int d2 = v >> 9;
            int j  = v & 511;
            const float* bh = d2 ? bhb : bhf;
            int te = d2 ? (T_ - 1 - t) : t;
            int gb = d2 * G3;

            float hg[3], xg[3];
            #pragma unroll
            for (int gate = 0; gate < 3; gate++) {
                int g = gb + gate*H_ + j;
                float s = bh[gate*H_ + j];
                #pragma unroll
                for (int c = 0; c < 4; c++)
                    s += __ldcg(&g_P[((size_t)g*4 + c) * B_ + pb_b]);
                hg[gate] = s;
                xg[gate] = __ldcg(&g_xpT[((size_t)te * GT + g) * B_ + pb_b]);
            }
            float r = 1.f / (1.f + __expf(-(xg[0] + hg[0])));
            float z = 1.f / (1.f + __expf(-(xg[1] + hg[1])));
            float n = tanhf(xg[2] + r * hg[2]);
            float* hp = &g_h[(d2*H_ + j) * B_ + pb_perm];   // PERMUTED slot
            float ho = __ldcg(hp);
            __stcg(hp, (1.f - z) * n + z * ho);
        }
        __threadfence();
        grid_barrier();
    }
}

// =================================================================================
// Phase 3: final FC + sigmoid (g_h slots are permuted -> index via permb)
// =================================================================================
__global__ void fc_kernel(const float* __restrict__ fcw,
                          const float* __restrict__ fcb,
                          float* __restrict__ out)
{
    int b  = threadIdx.x;           // 128 threads
    int pb = permb(b);
    float s = 0.f;
    for (int j = 0; j < 2*H_; j++)
        s = fmaf(g_h[j*B_ + pb], fcw[j], s);
    out[b] = 1.f / (1.f + __expf(-(s + fcb[0])));
}

// =================================================================================
extern "C" void kernel_launch(void* const* d_in, const int* in_sizes, int n_in,
                              void* d_out, int out_size)
{
    const int*   inputs = (const int*)  d_in[0];
    const float* emb    = (const float*)d_in[1];
    const float* Wihf   = (const float*)d_in[2];
    const float* Whhf   = (const float*)d_in[3];
    const float* bihf   = (const float*)d_in[4];
    const float* bhhf   = (const float*)d_in[5];
    const float* Wihb   = (const float*)d_in[6];
    const float* Whhb   = (const float*)d_in[7];
    const float* bihb   = (const float*)d_in[8];
    const float* bhhb   = (const float*)d_in[9];
    const float* fcw    = (const float*)d_in[10];
    const float* fcb    = (const float*)d_in[11];
    float* out = (float*)d_out;

    const int rec_smem = (128*192 + 128*128) * (int)sizeof(float);  // 160 KB
    cudaFuncSetAttribute(rec_kernel,
                         cudaFuncAttributeMaxDynamicSharedMemorySize, rec_smem);

    proj_kernel<<<dim3(T_, GT/128), 256>>>(inputs, emb, Wihf, Wihb, bihf, bihb);
    rec_kernel<<<NCTA_REC, REC_THREADS, rec_smem>>>(Whhf, Whhb, bhhf, bhhb);
    fc_kernel<<<1, B_>>>(fcw, fcb, out);

    (void)in_sizes; (void)n_in; (void)out_size;
}